// round 12
// baseline (speedup 1.0000x reference)
#include <cuda_runtime.h>
#include <cuda_bf16.h>
#include <mma.h>
#include <cstdint>

using namespace nvcuda;
typedef __nv_bfloat16 bf16;

// Problem constants
#define Bc   16
#define Nn_  128
#define Mm   1024
#define DN_  512
#define DE_  256
#define WN_  128
#define WE_  128
#define Pp   512
#define HID_ 256

// ---------------- scratch (static device globals; no allocation) -------------
__device__ float d_Xp [(size_t)Bc*Nn_*WN_];
__device__ float d_agg[(size_t)Bc*Nn_*WE_];
__device__ float d_hid[(size_t)Bc*Pp*768];
__device__ float d_nodeproj[(size_t)Bc*Nn_*768];
__device__ float d_b1cat[768];

__device__ __align__(128) bf16 d_T1h[(size_t)Bc*Mm*DE_];
__device__ __align__(128) bf16 d_T1l[(size_t)Bc*Mm*DE_];
__device__ __align__(128) bf16 d_T2h[(size_t)Bc*Nn_*DN_];
__device__ __align__(128) bf16 d_T2l[(size_t)Bc*Nn_*DN_];
__device__ __align__(128) bf16 d_Xh [(size_t)Bc*Nn_*DN_];
__device__ __align__(128) bf16 d_Xl [(size_t)Bc*Nn_*DN_];
__device__ __align__(128) bf16 d_efph[(size_t)Bc*Pp*DE_];
__device__ __align__(128) bf16 d_efpl[(size_t)Bc*Pp*DE_];
__device__ __align__(128) bf16 d_ncH [(size_t)Bc*Nn_*256];   // nodecat [h|agg*m]
__device__ __align__(128) bf16 d_ncL [(size_t)Bc*Nn_*256];
__device__ __align__(128) bf16 d_ciPh[(size_t)Bc*Pp*256];    // pair feats [Pm|Q]
__device__ __align__(128) bf16 d_ciPl[(size_t)Bc*Pp*256];
__device__ __align__(128) bf16 d_WtH[589824];
__device__ __align__(128) bf16 d_WtL[589824];

// ---------------- helpers -----------------------------------------------------
__device__ __forceinline__ void split_store(bf16* H, bf16* L, size_t idx, float v) {
    bf16 h = __float2bfloat16(v);
    H[idx] = h;
    L[idx] = __float2bfloat16(v - __bfloat162float(h));
}
__device__ __forceinline__ uint32_t bfpack(float a, float b) {
    __nv_bfloat162 p = __floats2bfloat162_rn(a, b);
    return *(uint32_t*)&p;
}
__device__ __forceinline__ uint32_t smem_u32(const void* p) {
    uint32_t a;
    asm("{ .reg .u64 t; cvta.to.shared.u64 t, %1; cvt.u32.u64 %0, t; }" : "=r"(a) : "l"(p));
    return a;
}
__device__ __forceinline__ void cpa16(uint32_t d, const void* s) {
    asm volatile("cp.async.cg.shared.global [%0], [%1], 16;" :: "r"(d), "l"(s));
}
#define CP_COMMIT() asm volatile("cp.async.commit_group;" ::: "memory")
#define CP_WAIT(n)  asm volatile("cp.async.wait_group %0;" :: "n"(n) : "memory")

// ---------------- L1: weights + bias + prep (ax | efp | zero) in ONE launch ---
struct WtTab {
    const float* W[10];
    int K[10], N[10];
    int off[10];
    int blkStart[11];
    const float *b0, *b1, *b2;
};
__global__ void k_mega1(WtTab tb, bf16* __restrict__ oh, bf16* __restrict__ ol,
                        float* __restrict__ bcat,
                        const float* __restrict__ nf, const float* __restrict__ adj,
                        const int* __restrict__ nob, const float* __restrict__ ef,
                        const int* __restrict__ op) {
    int bid = blockIdx.x, t = threadIdx.x;   // 256 threads
    int nw = tb.blkStart[10];
    if (bid < nw) {                                        // ---- weight split ----
        int mi = 0;
        while (bid >= tb.blkStart[mi + 1]) mi++;
        int id = (bid - tb.blkStart[mi]) * 256 + t;
        int K = tb.K[mi], N = tb.N[mi];
        if (id >= K * N) return;
        int n = id / K, k = id % K;
        float w = tb.W[mi][(size_t)k * N + n];
        split_store(oh + tb.off[mi], ol + tb.off[mi], id, w);
        return;
    }
    if (bid < nw + 3) {                                    // ---- bias concat ----
        int tt = (bid - nw) * 256 + t;
        const float* src = (tt < 256) ? tb.b0 : ((tt < 512) ? tb.b1 : tb.b2);
        bcat[tt] = src[tt & 255];
        return;
    }
    int pb = bid - nw - 3;
    if (pb < 2048) {                                       // ---- ax ----
        __shared__ int idxs[Nn_];
        __shared__ int cnt;
        int b = pb >> 7, i = pb & 127;
        int no = nob[b];
        size_t rbase = ((size_t)b * Nn_ + i) * DN_;
        if (t == 0) cnt = 0;
        __syncthreads();
        if (i >= no) {
            for (int c = t; c < DN_; c += 256) {
                d_Xh[rbase + c] = __float2bfloat16(0.f);  d_Xl[rbase + c] = __float2bfloat16(0.f);
                d_T2h[rbase + c] = __float2bfloat16(0.f); d_T2l[rbase + c] = __float2bfloat16(0.f);
            }
            return;
        }
        const float* arow = adj + ((size_t)b * Nn_ + i) * Nn_;
        const float* nfb  = nf  + (size_t)b * Nn_ * DN_;
        if (t < no && arow[t] != 0.f) { int p = atomicAdd(&cnt, 1); idxs[p] = t; }
        __syncthreads();
        int nn = cnt;
        for (int c = t; c < DN_; c += 256) {
            float x = nfb[(size_t)i * DN_ + c];
            float acc = x;
            for (int e = 0; e < nn; e++) acc += nfb[(size_t)idxs[e] * DN_ + c];
            split_store(d_Xh,  d_Xl,  rbase + c, x);
            split_store(d_T2h, d_T2l, rbase + c, acc);
        }
    } else if (pb < 2048 + 8192) {                         // ---- efp gather+split
        int id = pb - 2048;
        int b = id >> 9, p = id & 511;
        int p0 = op[((size_t)b * Pp + p) * 2 + 0];
        int p1 = op[((size_t)b * Pp + p) * 2 + 1];
        float v = ef[(((size_t)b * Nn_ + p0) * Nn_ + p1) * DE_ + t];
        split_store(d_efph, d_efpl, ((size_t)b * Pp + p) * DE_ + t, v);
    } else {                                               // ---- zero agg ----
        int z = pb - 2048 - 8192;                          // 1024 blocks
        d_agg[(size_t)z * 256 + t] = 0.f;
    }
}

// ---------------- K2: T1 = L @ gather(ef) directly (no d_Eg) ------------------
__global__ void k_lspmm(const float* __restrict__ ladj, const int* __restrict__ ned,
                        const float* __restrict__ ef, const int* __restrict__ ei) {
    int b = blockIdx.y, i = blockIdx.x, t = threadIdx.x;   // 256 threads
    int ne = ned[b];
    size_t rbase = ((size_t)b * Mm + i) * DE_;
    __shared__ int offs[Mm];
    __shared__ int cnt;
    if (t == 0) cnt = 0;
    __syncthreads();
    if (i >= ne) {
        d_T1h[rbase + t] = __float2bfloat16(0.f);
        d_T1l[rbase + t] = __float2bfloat16(0.f);
        return;
    }
    const int* ei0 = ei + (b * 2 + 0) * Mm;
    const int* ei1 = ei + (b * 2 + 1) * Mm;
    const float4* lrow4 = (const float4*)(ladj + ((size_t)b * Mm + i) * Mm);
    float4 v = lrow4[t];
    int base = t * 4;
    #pragma unroll
    for (int q = 0; q < 4; q++) {
        float lv = (q == 0) ? v.x : (q == 1) ? v.y : (q == 2) ? v.z : v.w;
        int j = base + q;
        if (j < ne && lv != 0.f) {
            int o = (ei0[j] * Nn_ + ei1[j]) * DE_;
            offs[atomicAdd(&cnt, 1)] = o;
        }
    }
    __syncthreads();
    int nn = cnt;
    const float* efb = ef + (size_t)b * Nn_ * Nn_ * DE_;
    float a0 = efb[(size_t)(ei0[i] * Nn_ + ei1[i]) * DE_ + t];
    float a1 = 0.f, a2 = 0.f, a3 = 0.f, a4 = 0.f, a5 = 0.f, a6 = 0.f, a7 = 0.f;
    int e = 0;
    for (; e + 8 <= nn; e += 8) {
        a0 += efb[(size_t)offs[e]     + t];
        a1 += efb[(size_t)offs[e + 1] + t];
        a2 += efb[(size_t)offs[e + 2] + t];
        a3 += efb[(size_t)offs[e + 3] + t];
        a4 += efb[(size_t)offs[e + 4] + t];
        a5 += efb[(size_t)offs[e + 5] + t];
        a6 += efb[(size_t)offs[e + 6] + t];
        a7 += efb[(size_t)offs[e + 7] + t];
    }
    for (; e < nn; e++) a0 += efb[(size_t)offs[e] + t];
    split_store(d_T1h, d_T1l, rbase + t,
                ((a0 + a1) + (a2 + a3)) + ((a4 + a5) + (a6 + a7)));
}

// ---------------- templated multi-segment wmma GEMM ---------------------------
#define F_RELU 1
#define F_BIAS 2
#define F_SPLIT 4
#define F_SCATTER 8
#define F_NODEADD 16
#define LDS_T 40          // bf16 row stride in stage

struct Seg {
    const bf16 *Ah, *Al, *Bh, *Bl;
    const float* bias;
    float* Cf;
    bf16 *Ch, *Cl;
    const int* ei;        // F_SCATTER: edge_index ; F_NODEADD: object_pairs
    float* agg;           // F_SCATTER: agg ; F_NODEADD: nodeproj
    int K, ldc, colOff, flags, nColBlk, blkEnd;
};
struct SegTable { Seg s[4]; int nseg; };

template<int TN, int MAXCTA>
__global__ void __launch_bounds__(256, MAXCTA)
wgemm_multi(SegTable tab) {
    constexpr int NACC = TN / 32;
    constexpr int LDS_S = TN + 4;
    constexpr int ABUF = 10240;
    constexpr int BBUF = TN * 80;
    constexpr int STAGE = 2 * ABUF + 2 * BBUF;

    extern __shared__ char smem[];
    int bid = blockIdx.x, t = threadIdx.x, wid = t >> 5;
    int si = 0;
    while (si + 1 < tab.nseg && bid >= tab.s[si].blkEnd) si++;
    const Seg sg = tab.s[si];
    int blk0 = (si == 0) ? 0 : tab.s[si - 1].blkEnd;
    int local = bid - blk0;
    int rb = (local / sg.nColBlk) * 128;
    int cb = (local % sg.nColBlk) * TN;
    const int K = sg.K;
    const int nch = K >> 5;

    const uint32_t sm = smem_u32(smem);
    const int row = t >> 1, part = t & 1;

    wmma::fragment<wmma::accumulator, 16, 16, 16, float> acc[2][NACC];
    #pragma unroll
    for (int m = 0; m < 2; m++)
        #pragma unroll
        for (int n = 0; n < NACC; n++) wmma::fill_fragment(acc[m][n], 0.0f);
    int wm = wid & 3, wn = wid >> 2;   // warp tile: rows wm*32, cols wn*(TN/2)

    auto load_chunk = [&](int kc, int buf) {
        uint32_t sbase = sm + buf * STAGE;
        const char* aH = (const char*)(sg.Ah + (size_t)(rb + row) * K + kc * 32) + part * 32;
        const char* aL = (const char*)(sg.Al + (size_t)(rb + row) * K + kc * 32) + part * 32;
        uint32_t d0 = sbase + row * 80 + part * 32;
        cpa16(d0, aH);            cpa16(d0 + 16, aH + 16);
        cpa16(d0 + ABUF, aL);     cpa16(d0 + ABUF + 16, aL + 16);
        if (TN == 128) {
            int brow = t >> 1, bp = t & 1;
            const char* bH = (const char*)(sg.Bh + (size_t)(cb + brow) * K + kc * 32) + bp * 32;
            const char* bL = (const char*)(sg.Bl + (size_t)(cb + brow) * K + kc * 32) + bp * 32;
            uint32_t d1 = sbase + 2 * ABUF + brow * 80 + bp * 32;
            cpa16(d1, bH);           cpa16(d1 + 16, bH + 16);
            cpa16(d1 + BBUF, bL);    cpa16(d1 + BBUF + 16, bL + 16);
        } else {
            int brow = t >> 2, bp = t & 3;
            const char* bH = (const char*)(sg.Bh + (size_t)(cb + brow) * K + kc * 32) + bp * 16;
            const char* bL = (const char*)(sg.Bl + (size_t)(cb + brow) * K + kc * 32) + bp * 16;
            uint32_t d1 = sbase + 2 * ABUF + brow * 80 + bp * 16;
            cpa16(d1, bH);
            cpa16(d1 + BBUF, bL);
        }
    };

    load_chunk(0, 0);
    CP_COMMIT();
    for (int kc = 0; kc < nch; kc++) {
        if (kc + 1 < nch) { load_chunk(kc + 1, (kc + 1) & 1); CP_COMMIT(); CP_WAIT(1); }
        else              { CP_WAIT(0); }
        __syncthreads();
        const bf16* Ahs = (const bf16*)(smem + (kc & 1) * STAGE);
        const bf16* Als = Ahs + ABUF / 2;
        const bf16* Bhs = Ahs + ABUF;
        const bf16* Bls = Bhs + BBUF / 2;
        #pragma unroll
        for (int kk = 0; kk < 2; kk++) {
            wmma::fragment<wmma::matrix_a, 16, 16, 16, bf16, wmma::row_major> fah[2], fal[2];
            #pragma unroll
            for (int m = 0; m < 2; m++) {
                wmma::load_matrix_sync(fah[m], Ahs + (wm * 32 + m * 16) * LDS_T + kk * 16, LDS_T);
                wmma::load_matrix_sync(fal[m], Als + (wm * 32 + m * 16) * LDS_T + kk * 16, LDS_T);
            }
            #pragma unroll
            for (int n = 0; n < NACC; n++) {
                wmma::fragment<wmma::matrix_b, 16, 16, 16, bf16, wmma::col_major> fbh, fbl;
                wmma::load_matrix_sync(fbh, Bhs + (wn * (TN / 2) + n * 16) * LDS_T + kk * 16, LDS_T);
                wmma::load_matrix_sync(fbl, Bls + (wn * (TN / 2) + n * 16) * LDS_T + kk * 16, LDS_T);
                #pragma unroll
                for (int m = 0; m < 2; m++) {
                    wmma::mma_sync(acc[m][n], fah[m], fbh, acc[m][n]);
                    wmma::mma_sync(acc[m][n], fah[m], fbl, acc[m][n]);
                    wmma::mma_sync(acc[m][n], fal[m], fbh, acc[m][n]);
                }
            }
        }
        __syncthreads();
    }

    // ---- epilogue ----
    float* stage = (float*)smem;                    // [128][LDS_S]
    #pragma unroll
    for (int m = 0; m < 2; m++)
        #pragma unroll
        for (int n = 0; n < NACC; n++)
            wmma::store_matrix_sync(stage + (wm * 32 + m * 16) * LDS_S + wn * (TN / 2) + n * 16,
                                    acc[m][n], LDS_S, wmma::mem_row_major);
    __syncthreads();
    int r = t >> 1, ch = (t & 1) * (TN / 2);
    const float* srow = stage + r * LDS_S + ch;
    if (sg.flags & F_SCATTER) {
        int m = rb + r, b = m >> 10, mm = m & 1023;
        int s = sg.ei[(b * 2) * Mm + mm];
        float* dst = sg.agg + ((size_t)(b * Nn_ + s)) * WE_ + cb + ch;
        #pragma unroll 8
        for (int q = 0; q < TN / 2; q++) {
            float v = fmaxf(srow[q], 0.f);
            if (v != 0.f) atomicAdd(dst + q, v);
        }
    } else if (sg.flags & F_SPLIT) {
        size_t base = (size_t)(rb + r) * sg.ldc + sg.colOff + cb + ch;
        uint32_t* CH = (uint32_t*)(sg.Ch + base);
        uint32_t* CL = (uint32_t*)(sg.Cl + base);
        #pragma unroll 4
        for (int q = 0; q < TN / 4; q++) {
            float v0 = srow[2 * q], v1 = srow[2 * q + 1];
            if (sg.flags & F_RELU) { v0 = fmaxf(v0, 0.f); v1 = fmaxf(v1, 0.f); }
            bf16 h0 = __float2bfloat16(v0), h1 = __float2bfloat16(v1);
            float l0 = v0 - __bfloat162float(h0), l1 = v1 - __bfloat162float(h1);
            CH[q] = (uint32_t)__bfloat16_as_ushort(h0) | ((uint32_t)__bfloat16_as_ushort(h1) << 16);
            CL[q] = bfpack(l0, l1);
        }
    } else if (sg.flags & F_NODEADD) {
        int pair = rb + r, b = pair >> 9, p = pair & 511;
        int p0 = sg.ei[((size_t)b * Pp + p) * 2 + 0];
        int p1 = sg.ei[((size_t)b * Pp + p) * 2 + 1];
        int gc0 = cb + ch;
        const float* np0 = sg.agg + ((size_t)(b * Nn_ + p0)) * 768 + gc0;
        const float* np1 = sg.agg + ((size_t)(b * Nn_ + p1)) * 768 + gc0;
        float* crow = sg.Cf + (size_t)pair * sg.ldc + gc0;
        #pragma unroll 4
        for (int q = 0; q < TN / 8; q++) {
            float4 v = *(const float4*)(srow + q * 4);
            float4 a = *(const float4*)(np0 + q * 4);
            float4 c2 = *(const float4*)(np1 + q * 4);
            v.x = fmaxf(v.x + a.x + c2.x + sg.bias[gc0 + q * 4 + 0], 0.f);
            v.y = fmaxf(v.y + a.y + c2.y + sg.bias[gc0 + q * 4 + 1], 0.f);
            v.z = fmaxf(v.z + a.z + c2.z + sg.bias[gc0 + q * 4 + 2], 0.f);
            v.w = fmaxf(v.w + a.w + c2.w + sg.bias[gc0 + q * 4 + 3], 0.f);
            *(float4*)(crow + q * 4) = v;
        }
    } else {
        float* crow = sg.Cf + (size_t)(rb + r) * sg.ldc + cb + ch;
        #pragma unroll 4
        for (int q = 0; q < TN / 8; q++) {
            float4 v = *(const float4*)(srow + q * 4);
            if (sg.flags & F_BIAS) {
                int gc = cb + ch + q * 4;
                v.x += sg.bias[gc + 0]; v.y += sg.bias[gc + 1];
                v.z += sg.bias[gc + 2]; v.w += sg.bias[gc + 3];
            }
            if (sg.flags & F_RELU) {
                v.x = fmaxf(v.x, 0.f); v.y = fmaxf(v.y, 0.f);
                v.z = fmaxf(v.z, 0.f); v.w = fmaxf(v.w, 0.f);
            }
            *(float4*)(crow + q * 4) = v;
        }
    }
}

// ---------------- K5: pair Pm + agg*mask, 4 rows/block, float2 ----------------
__global__ void k_ci(const int* __restrict__ op, const int* __restrict__ nob) {
    int bid = blockIdx.x, t = threadIdx.x;   // 256 threads
    int sub = t >> 6, tt = (t & 63) * 2;     // 4 rows/block, 2 cols/thread
    if (bid < 2048) {                        // ---- Pm: pairs ----
        int pr = bid * 4 + sub;
        int b = pr >> 9, p = pr & 511;
        int p0 = op[((size_t)b * Pp + p) * 2 + 0];
        int p1 = op[((size_t)b * Pp + p) * 2 + 1];
        float2 x0 = *(const float2*)(d_Xp + ((size_t)b * Nn_ + p0) * WN_ + tt);
        float2 x1 = *(const float2*)(d_Xp + ((size_t)b * Nn_ + p1) * WN_ + tt);
        float v0 = fmaxf(x0.x + x1.x, 0.f);
        float v1 = fmaxf(x0.y + x1.y, 0.f);
        size_t base = (size_t)pr * 256 + tt;
        bf16 h0 = __float2bfloat16(v0), h1 = __float2bfloat16(v1);
        *(uint32_t*)(d_ciPh + base) =
            (uint32_t)__bfloat16_as_ushort(h0) | ((uint32_t)__bfloat16_as_ushort(h1) << 16);
        *(uint32_t*)(d_ciPl + base) =
            bfpack(v0 - __bfloat162float(h0), v1 - __bfloat162float(h1));
    } else {                                 // ---- nodecat agg half ----
        int row = (bid - 2048) * 4 + sub;
        int b = row >> 7, i = row & 127;
        float m = (i < nob[b]) ? 1.f : 0.f;
        float2 a = *(const float2*)(d_agg + (size_t)row * 128 + tt);
        float v0 = a.x * m, v1 = a.y * m;
        size_t base = (size_t)row * 256 + 128 + tt;
        bf16 h0 = __float2bfloat16(v0), h1 = __float2bfloat16(v1);
        *(uint32_t*)(d_ncH + base) =
            (uint32_t)__bfloat16_as_ushort(h0) | ((uint32_t)__bfloat16_as_ushort(h1) << 16);
        *(uint32_t*)(d_ncL + base) =
            bfpack(v0 - __bfloat162float(h0), v1 - __bfloat162float(h1));
    }
}

// ---------------- K7: MLP layer 2 — 16 rows/block, W2 staged in smem ----------
__global__ void __launch_bounds__(256)
k_head(const float* __restrict__ Wl, const float* __restrict__ bl,
       const float* __restrict__ Wc, const float* __restrict__ bc,
       const float* __restrict__ Wm, const float* __restrict__ bm,
       float* __restrict__ out) {
    __shared__ float W2s[256 * 33];          // padded stride 33 (conflict-free)
    __shared__ float bs[32];
    __shared__ float hs[768];
    int t = threadIdx.x;                     // 256
    // stage combined W2 [256 k][32 out] (cols: 0-8 lr, 9-14 cr, 15-31 mr)
    for (int idx = t; idx < 8192; idx += 256) {
        int k = idx >> 5, c = idx & 31;
        float w = (c < 9) ? Wl[(size_t)k * 9 + c]
                 : (c < 15) ? Wc[(size_t)k * 6 + (c - 9)]
                 : Wm[(size_t)k * 17 + (c - 15)];
        W2s[k * 33 + c] = w;
    }
    if (t < 32)
        bs[t] = (t < 9) ? bl[t] : (t < 15) ? bc[t - 9] : bm[t - 15];
    __syncthreads();

    int o = t >> 3, l = t & 7;               // 32 outputs x 8 lanes
    int hbase = (o < 9) ? 0 : (o < 15) ? 256 : 512;
    int r0 = blockIdx.x * 16;
    for (int rr = 0; rr < 16; rr++) {
        int r = r0 + rr;
        for (int c = t; c < 768; c += 256) hs[c] = d_hid[(size_t)r * 768 + c];
        __syncthreads();
        float s = 0.f;
        #pragma unroll 8
        for (int k = l; k < 256; k += 8) s += hs[hbase + k] * W2s[k * 33 + o];
        #pragma unroll
        for (int off = 4; off; off >>= 1) s += __shfl_down_sync(0xffffffffu, s, off, 8);
        if (l == 0) {
            float v = s + bs[o];
            if (o < 9)       out[(size_t)r * 9 + o] = v;
            else if (o < 15) out[73728  + (size_t)r * 6  + (o - 9)]  = v;
            else             out[122880 + (size_t)r * 17 + (o - 15)] = v;
        }
        __syncthreads();
    }
}

// ---------------- launch -----------------------------------------------------
extern "C" void kernel_launch(void* const* d_in, const int* in_sizes, int n_in,
                              void* d_out, int out_size) {
    const float* nf   = (const float*)d_in[0];
    const float* ef   = (const float*)d_in[1];
    const float* adj  = (const float*)d_in[2];
    const float* ladj = (const float*)d_in[3];
    const int*   ei   = (const int*)  d_in[4];
    const int*   op   = (const int*)  d_in[5];
    const int*   nob  = (const int*)  d_in[6];
    const int*   ned  = (const int*)  d_in[7];
    const float* Wn   = (const float*)d_in[8];
    const float* We   = (const float*)d_in[9];
    const float* Wn2  = (const float*)d_in[10];
    const float* We2  = (const float*)d_in[11];
    const float* scrW1= (const float*)d_in[12];
    const float* scrb1= (const float*)d_in[13];
    const float* scrW2= (const float*)d_in[14];
    const float* scrb2= (const float*)d_in[15];
    const float* lrW1 = (const float*)d_in[16];
    const float* lrb1 = (const float*)d_in[17];
    const float* lrW2 = (const float*)d_in[18];
    const float* lrb2 = (const float*)d_in[19];
    const float* mrW1 = (const float*)d_in[20];
    const float* mrb1 = (const float*)d_in[21];
    const float* mrW2 = (const float*)d_in[22];
    const float* mrb2 = (const float*)d_in[23];
    float* out = (float*)d_out;

    bf16 *pWtH, *pWtL, *pT1h, *pT1l, *pT2h, *pT2l, *pXh, *pXl, *pEfph, *pEfpl;
    bf16 *pNcH, *pNcL, *pCiPh, *pCiPl;
    float *pXp, *pAgg, *pHid, *pB1, *pNp;
    cudaGetSymbolAddress((void**)&pWtH, d_WtH);
    cudaGetSymbolAddress((void**)&pWtL, d_WtL);
    cudaGetSymbolAddress((void**)&pT1h, d_T1h);
    cudaGetSymbolAddress((void**)&pT1l, d_T1l);
    cudaGetSymbolAddress((void**)&pT2h, d_T2h);
    cudaGetSymbolAddress((void**)&pT2l, d_T2l);
    cudaGetSymbolAddress((void**)&pXh,  d_Xh);
    cudaGetSymbolAddress((void**)&pXl,  d_Xl);
    cudaGetSymbolAddress((void**)&pEfph,d_efph);
    cudaGetSymbolAddress((void**)&pEfpl,d_efpl);
    cudaGetSymbolAddress((void**)&pNcH, d_ncH);
    cudaGetSymbolAddress((void**)&pNcL, d_ncL);
    cudaGetSymbolAddress((void**)&pCiPh,d_ciPh);
    cudaGetSymbolAddress((void**)&pCiPl,d_ciPl);
    cudaGetSymbolAddress((void**)&pXp,  d_Xp);
    cudaGetSymbolAddress((void**)&pAgg, d_agg);
    cudaGetSymbolAddress((void**)&pHid, d_hid);
    cudaGetSymbolAddress((void**)&pB1,  d_b1cat);
    cudaGetSymbolAddress((void**)&pNp,  d_nodeproj);

    const int SMEM64  = 2 * (2 * 10240 + 2 * 64 * 80);    // 61440
    const int SMEM128 = 2 * (2 * 10240 + 2 * 128 * 80);   // 81920
    cudaFuncSetAttribute(wgemm_multi<64, 3>,  cudaFuncAttributeMaxDynamicSharedMemorySize, SMEM64);
    cudaFuncSetAttribute(wgemm_multi<128, 2>, cudaFuncAttributeMaxDynamicSharedMemorySize, SMEM128);

    // d_Wt layout (elems): We[0,32768) Wn[32768,98304) Wn2[98304,163840)
    //                      We2[163840,196608) Wa[196608,393216) Wb[393216,589824)
    const int oWe = 0, oWn = 32768, oWn2 = 98304, oWe2 = 163840, oWa = 196608, oWb = 393216;
    WtTab wt;
    const float* Ws[10] = {We, Wn, Wn2, We2,
                           lrW1, lrW1 + 256 * 256,
                           scrW1, scrW1 + 256 * 256,
                           mrW1, mrW1 + 256 * 256};
    int Ks[10] = {256, 512, 512, 256, 256, 256, 256, 256, 256, 256};
    int Ns[10] = {128, 128, 128, 128, 256, 256, 256, 256, 256, 256};
    int offs[10] = {oWe, oWn, oWn2, oWe2,
                    oWa, oWb, oWa + 65536, oWb + 65536, oWa + 131072, oWb + 131072};
    int bs = 0;
    for (int i = 0; i < 10; i++) {
        wt.W[i] = Ws[i]; wt.K[i] = Ks[i]; wt.N[i] = Ns[i]; wt.off[i] = offs[i];
        wt.blkStart[i] = bs;
        bs += (Ks[i] * Ns[i]) / 256;
    }
    wt.blkStart[10] = bs;
    wt.b0 = lrb1; wt.b1 = scrb1; wt.b2 = mrb1;

    // ---- L1: weights + prep (one launch) ----
    int megaBlocks = bs + 3 + 2048 + 8192 + 1024;
    k_mega1<<<megaBlocks, 256>>>(wt, pWtH, pWtL, pB1, nf, adj, nob, ef, op);

    // ---- L2: line-graph SpMM, gathers straight from ef ----
    k_lspmm<<<dim3(Mm, Bc), 256>>>(ladj, ned, ef, ei);

    // ---- L3: wave-1 (TN=64): g(scatter) + h(->nodecat split) + Xp + Q(->ciP) -
    SegTable t4 = {};
    t4.nseg = 4;
    t4.s[0] = {pT1h, pT1l, pWtH + oWe, pWtL + oWe, nullptr, nullptr, nullptr, nullptr,
               ei, pAgg, 256, 0, 0, F_RELU | F_SCATTER, 2, 256};
    t4.s[1] = {pT2h, pT2l, pWtH + oWn, pWtL + oWn, nullptr, nullptr, pNcH, pNcL,
               nullptr, nullptr, 512, 256, 0, F_RELU | F_SPLIT, 2, 288};
    t4.s[2] = {pXh, pXl, pWtH + oWn2, pWtL + oWn2, nullptr, pXp, nullptr, nullptr,
               nullptr, nullptr, 512, 128, 0, 0, 2, 320};
    t4.s[3] = {pEfph, pEfpl, pWtH + oWe2, pWtL + oWe2, nullptr, nullptr, pCiPh, pCiPl,
               nullptr, nullptr, 256, 256, 128, F_RELU | F_SPLIT, 2, 448};
    wgemm_multi<64, 3><<<448, 256, SMEM64>>>(t4);

    // ---- L4: ciP Pm + nodecat agg-half (4 rows/block, float2) ----
    k_ci<<<2560, 256>>>(op, nob);

    // ---- L5: node GEMM: nodeproj = nodecat @ Wa  [2048 x 768 x 256] ----
    SegTable tn = {};
    tn.nseg = 1;
    tn.s[0] = {pNcH, pNcL, pWtH + oWa, pWtL + oWa, nullptr, pNp, nullptr, nullptr,
               nullptr, nullptr, 256, 768, 0, 0, 12, 192};
    wgemm_multi<64, 3><<<192, 256, SMEM64>>>(tn);

    // ---- L6: pair GEMM: hid = relu(ciP @ Wb + np[p0] + np[p1] + b) ----------
    SegTable tp = {};
    tp.nseg = 1;
    tp.s[0] = {pCiPh, pCiPl, pWtH + oWb, pWtL + oWb, pB1, pHid, nullptr, nullptr,
               op, pNp, 256, 768, 0, F_RELU | F_BIAS | F_NODEADD, 6, 384};
    wgemm_multi<128, 2><<<384, 256, SMEM128>>>(tp);

    // ---- L7: MLP layer 2 -> out (512 blocks, 16 rows each, W2 in smem) ----
    k_head<<<512, 256>>>(lrW2, lrb2, scrW2, scrb2, mrW2, mrb2, out);
}

// round 13
// speedup vs baseline: 1.1834x; 1.1834x over previous
#include <cuda_runtime.h>
#include <cuda_bf16.h>
#include <mma.h>
#include <cstdint>

using namespace nvcuda;
typedef __nv_bfloat16 bf16;

// Problem constants
#define Bc   16
#define Nn_  128
#define Mm   1024
#define DN_  512
#define DE_  256
#define WN_  128
#define WE_  128
#define Pp   512
#define HID_ 256

// ---------------- scratch (static device globals; no allocation) -------------
__device__ float d_Xp [(size_t)Bc*Nn_*WN_];
__device__ float d_agg[(size_t)Bc*Nn_*WE_];
__device__ float d_hid[(size_t)Bc*Pp*768];
__device__ float d_nodeproj[(size_t)Bc*Nn_*768];
__device__ float d_b1cat[768];

__device__ __align__(128) bf16 d_T1h[(size_t)Bc*Mm*DE_];
__device__ __align__(128) bf16 d_T1l[(size_t)Bc*Mm*DE_];
__device__ __align__(128) bf16 d_T2h[(size_t)Bc*Nn_*DN_];
__device__ __align__(128) bf16 d_T2l[(size_t)Bc*Nn_*DN_];
__device__ __align__(128) bf16 d_Xh [(size_t)Bc*Nn_*DN_];
__device__ __align__(128) bf16 d_Xl [(size_t)Bc*Nn_*DN_];
__device__ __align__(128) bf16 d_efph[(size_t)Bc*Pp*DE_];
__device__ __align__(128) bf16 d_efpl[(size_t)Bc*Pp*DE_];
__device__ __align__(128) bf16 d_ncH [(size_t)Bc*Nn_*256];   // nodecat [h|agg*m]
__device__ __align__(128) bf16 d_ncL [(size_t)Bc*Nn_*256];
__device__ __align__(128) bf16 d_ciPh[(size_t)Bc*Pp*256];    // pair feats [Pm|Q]
__device__ __align__(128) bf16 d_ciPl[(size_t)Bc*Pp*256];
__device__ __align__(128) bf16 d_WtH[589824];
__device__ __align__(128) bf16 d_WtL[589824];

// ---------------- helpers -----------------------------------------------------
__device__ __forceinline__ void split_store(bf16* H, bf16* L, size_t idx, float v) {
    bf16 h = __float2bfloat16(v);
    H[idx] = h;
    L[idx] = __float2bfloat16(v - __bfloat162float(h));
}
__device__ __forceinline__ uint32_t bfpack(float a, float b) {
    __nv_bfloat162 p = __floats2bfloat162_rn(a, b);
    return *(uint32_t*)&p;
}
__device__ __forceinline__ uint32_t smem_u32(const void* p) {
    uint32_t a;
    asm("{ .reg .u64 t; cvta.to.shared.u64 t, %1; cvt.u32.u64 %0, t; }" : "=r"(a) : "l"(p));
    return a;
}
__device__ __forceinline__ void cpa16(uint32_t d, const void* s) {
    asm volatile("cp.async.cg.shared.global [%0], [%1], 16;" :: "r"(d), "l"(s));
}
#define CP_COMMIT() asm volatile("cp.async.commit_group;" ::: "memory")
#define CP_WAIT(n)  asm volatile("cp.async.wait_group %0;" :: "n"(n) : "memory")

// ---------------- L1: weights + bias + prep (ax | efp | zero) in ONE launch ---
struct WtTab {
    const float* W[10];
    int K[10], N[10];
    int off[10];
    int blkStart[11];
    const float *b0, *b1, *b2;
};
__global__ void k_mega1(WtTab tb, bf16* __restrict__ oh, bf16* __restrict__ ol,
                        float* __restrict__ bcat,
                        const float* __restrict__ nf, const float* __restrict__ adj,
                        const int* __restrict__ nob, const float* __restrict__ ef,
                        const int* __restrict__ op) {
    int bid = blockIdx.x, t = threadIdx.x;   // 256 threads
    int nw = tb.blkStart[10];
    if (bid < nw) {                                        // ---- weight split ----
        int mi = 0;
        while (bid >= tb.blkStart[mi + 1]) mi++;
        int id = (bid - tb.blkStart[mi]) * 256 + t;
        int K = tb.K[mi], N = tb.N[mi];
        if (id >= K * N) return;
        int n = id / K, k = id % K;
        float w = tb.W[mi][(size_t)k * N + n];
        split_store(oh + tb.off[mi], ol + tb.off[mi], id, w);
        return;
    }
    if (bid < nw + 3) {                                    // ---- bias concat ----
        int tt = (bid - nw) * 256 + t;
        const float* src = (tt < 256) ? tb.b0 : ((tt < 512) ? tb.b1 : tb.b2);
        bcat[tt] = src[tt & 255];
        return;
    }
    int pb = bid - nw - 3;
    if (pb < 2048) {                                       // ---- ax ----
        __shared__ int idxs[Nn_];
        __shared__ int cnt;
        int b = pb >> 7, i = pb & 127;
        int no = nob[b];
        size_t rbase = ((size_t)b * Nn_ + i) * DN_;
        if (t == 0) cnt = 0;
        __syncthreads();
        if (i >= no) {
            for (int c = t; c < DN_; c += 256) {
                d_Xh[rbase + c] = __float2bfloat16(0.f);  d_Xl[rbase + c] = __float2bfloat16(0.f);
                d_T2h[rbase + c] = __float2bfloat16(0.f); d_T2l[rbase + c] = __float2bfloat16(0.f);
            }
            return;
        }
        const float* arow = adj + ((size_t)b * Nn_ + i) * Nn_;
        const float* nfb  = nf  + (size_t)b * Nn_ * DN_;
        if (t < no && arow[t] != 0.f) { int p = atomicAdd(&cnt, 1); idxs[p] = t; }
        __syncthreads();
        int nn = cnt;
        for (int c = t; c < DN_; c += 256) {
            float x = nfb[(size_t)i * DN_ + c];
            float acc = x;
            for (int e = 0; e < nn; e++) acc += nfb[(size_t)idxs[e] * DN_ + c];
            split_store(d_Xh,  d_Xl,  rbase + c, x);
            split_store(d_T2h, d_T2l, rbase + c, acc);
        }
    } else if (pb < 2048 + 8192) {                         // ---- efp gather+split
        int id = pb - 2048;
        int b = id >> 9, p = id & 511;
        int p0 = op[((size_t)b * Pp + p) * 2 + 0];
        int p1 = op[((size_t)b * Pp + p) * 2 + 1];
        float v = ef[(((size_t)b * Nn_ + p0) * Nn_ + p1) * DE_ + t];
        split_store(d_efph, d_efpl, ((size_t)b * Pp + p) * DE_ + t, v);
    } else {                                               // ---- zero agg ----
        int z = pb - 2048 - 8192;                          // 1024 blocks
        d_agg[(size_t)z * 256 + t] = 0.f;
    }
}

// ---------------- K2: T1 = L @ gather(ef) directly (no d_Eg) ------------------
__global__ void k_lspmm(const float* __restrict__ ladj, const int* __restrict__ ned,
                        const float* __restrict__ ef, const int* __restrict__ ei) {
    int b = blockIdx.y, i = blockIdx.x, t = threadIdx.x;   // 256 threads
    int ne = ned[b];
    size_t rbase = ((size_t)b * Mm + i) * DE_;
    __shared__ int offs[Mm];
    __shared__ int cnt;
    if (t == 0) cnt = 0;
    __syncthreads();
    if (i >= ne) {
        d_T1h[rbase + t] = __float2bfloat16(0.f);
        d_T1l[rbase + t] = __float2bfloat16(0.f);
        return;
    }
    const int* ei0 = ei + (b * 2 + 0) * Mm;
    const int* ei1 = ei + (b * 2 + 1) * Mm;
    const float4* lrow4 = (const float4*)(ladj + ((size_t)b * Mm + i) * Mm);
    float4 v = lrow4[t];
    int base = t * 4;
    #pragma unroll
    for (int q = 0; q < 4; q++) {
        float lv = (q == 0) ? v.x : (q == 1) ? v.y : (q == 2) ? v.z : v.w;
        int j = base + q;
        if (j < ne && lv != 0.f) {
            int o = (ei0[j] * Nn_ + ei1[j]) * DE_;
            offs[atomicAdd(&cnt, 1)] = o;
        }
    }
    __syncthreads();
    int nn = cnt;
    const float* efb = ef + (size_t)b * Nn_ * Nn_ * DE_;
    float a0 = efb[(size_t)(ei0[i] * Nn_ + ei1[i]) * DE_ + t];
    float a1 = 0.f, a2 = 0.f, a3 = 0.f, a4 = 0.f, a5 = 0.f, a6 = 0.f, a7 = 0.f;
    int e = 0;
    for (; e + 8 <= nn; e += 8) {
        a0 += efb[(size_t)offs[e]     + t];
        a1 += efb[(size_t)offs[e + 1] + t];
        a2 += efb[(size_t)offs[e + 2] + t];
        a3 += efb[(size_t)offs[e + 3] + t];
        a4 += efb[(size_t)offs[e + 4] + t];
        a5 += efb[(size_t)offs[e + 5] + t];
        a6 += efb[(size_t)offs[e + 6] + t];
        a7 += efb[(size_t)offs[e + 7] + t];
    }
    for (; e < nn; e++) a0 += efb[(size_t)offs[e] + t];
    split_store(d_T1h, d_T1l, rbase + t,
                ((a0 + a1) + (a2 + a3)) + ((a4 + a5) + (a6 + a7)));
}

// ---------------- templated multi-segment wmma GEMM ---------------------------
#define F_RELU 1
#define F_BIAS 2
#define F_SPLIT 4
#define F_SCATTER 8
#define F_NODEADD 16
#define LDS_T 40          // bf16 row stride in stage

struct Seg {
    const bf16 *Ah, *Al, *Bh, *Bl;
    const float* bias;
    float* Cf;
    bf16 *Ch, *Cl;
    const int* ei;        // F_SCATTER: edge_index ; F_NODEADD: object_pairs
    float* agg;           // F_SCATTER: agg ; F_NODEADD: nodeproj
    int K, ldc, colOff, flags, nColBlk, blkEnd;
};
struct SegTable { Seg s[4]; int nseg; };

template<int TN, int MAXCTA>
__global__ void __launch_bounds__(256, MAXCTA)
wgemm_multi(SegTable tab) {
    constexpr int NACC = TN / 32;
    constexpr int LDS_S = TN + 4;
    constexpr int ABUF = 10240;
    constexpr int BBUF = TN * 80;
    constexpr int STAGE = 2 * ABUF + 2 * BBUF;

    extern __shared__ char smem[];
    int bid = blockIdx.x, t = threadIdx.x, wid = t >> 5;
    int si = 0;
    while (si + 1 < tab.nseg && bid >= tab.s[si].blkEnd) si++;
    const Seg sg = tab.s[si];
    int blk0 = (si == 0) ? 0 : tab.s[si - 1].blkEnd;
    int local = bid - blk0;
    int rb = (local / sg.nColBlk) * 128;
    int cb = (local % sg.nColBlk) * TN;
    const int K = sg.K;
    const int nch = K >> 5;

    const uint32_t sm = smem_u32(smem);
    const int row = t >> 1, part = t & 1;

    wmma::fragment<wmma::accumulator, 16, 16, 16, float> acc[2][NACC];
    #pragma unroll
    for (int m = 0; m < 2; m++)
        #pragma unroll
        for (int n = 0; n < NACC; n++) wmma::fill_fragment(acc[m][n], 0.0f);
    int wm = wid & 3, wn = wid >> 2;   // warp tile: rows wm*32, cols wn*(TN/2)

    auto load_chunk = [&](int kc, int buf) {
        uint32_t sbase = sm + buf * STAGE;
        const char* aH = (const char*)(sg.Ah + (size_t)(rb + row) * K + kc * 32) + part * 32;
        const char* aL = (const char*)(sg.Al + (size_t)(rb + row) * K + kc * 32) + part * 32;
        uint32_t d0 = sbase + row * 80 + part * 32;
        cpa16(d0, aH);            cpa16(d0 + 16, aH + 16);
        cpa16(d0 + ABUF, aL);     cpa16(d0 + ABUF + 16, aL + 16);
        if (TN == 128) {
            int brow = t >> 1, bp = t & 1;
            const char* bH = (const char*)(sg.Bh + (size_t)(cb + brow) * K + kc * 32) + bp * 32;
            const char* bL = (const char*)(sg.Bl + (size_t)(cb + brow) * K + kc * 32) + bp * 32;
            uint32_t d1 = sbase + 2 * ABUF + brow * 80 + bp * 32;
            cpa16(d1, bH);           cpa16(d1 + 16, bH + 16);
            cpa16(d1 + BBUF, bL);    cpa16(d1 + BBUF + 16, bL + 16);
        } else {
            int brow = t >> 2, bp = t & 3;
            const char* bH = (const char*)(sg.Bh + (size_t)(cb + brow) * K + kc * 32) + bp * 16;
            const char* bL = (const char*)(sg.Bl + (size_t)(cb + brow) * K + kc * 32) + bp * 16;
            uint32_t d1 = sbase + 2 * ABUF + brow * 80 + bp * 16;
            cpa16(d1, bH);
            cpa16(d1 + BBUF, bL);
        }
    };

    load_chunk(0, 0);
    CP_COMMIT();
    for (int kc = 0; kc < nch; kc++) {
        if (kc + 1 < nch) { load_chunk(kc + 1, (kc + 1) & 1); CP_COMMIT(); CP_WAIT(1); }
        else              { CP_WAIT(0); }
        __syncthreads();
        const bf16* Ahs = (const bf16*)(smem + (kc & 1) * STAGE);
        const bf16* Als = Ahs + ABUF / 2;
        const bf16* Bhs = Ahs + ABUF;
        const bf16* Bls = Bhs + BBUF / 2;
        #pragma unroll
        for (int kk = 0; kk < 2; kk++) {
            wmma::fragment<wmma::matrix_a, 16, 16, 16, bf16, wmma::row_major> fah[2], fal[2];
            #pragma unroll
            for (int m = 0; m < 2; m++) {
                wmma::load_matrix_sync(fah[m], Ahs + (wm * 32 + m * 16) * LDS_T + kk * 16, LDS_T);
                wmma::load_matrix_sync(fal[m], Als + (wm * 32 + m * 16) * LDS_T + kk * 16, LDS_T);
            }
            #pragma unroll
            for (int n = 0; n < NACC; n++) {
                wmma::fragment<wmma::matrix_b, 16, 16, 16, bf16, wmma::col_major> fbh, fbl;
                wmma::load_matrix_sync(fbh, Bhs + (wn * (TN / 2) + n * 16) * LDS_T + kk * 16, LDS_T);
                wmma::load_matrix_sync(fbl, Bls + (wn * (TN / 2) + n * 16) * LDS_T + kk * 16, LDS_T);
                #pragma unroll
                for (int m = 0; m < 2; m++) {
                    wmma::mma_sync(acc[m][n], fah[m], fbh, acc[m][n]);
                    wmma::mma_sync(acc[m][n], fah[m], fbl, acc[m][n]);
                    wmma::mma_sync(acc[m][n], fal[m], fbh, acc[m][n]);
                }
            }
        }
        __syncthreads();
    }

    // ---- epilogue ----
    float* stage = (float*)smem;                    // [128][LDS_S]
    #pragma unroll
    for (int m = 0; m < 2; m++)
        #pragma unroll
        for (int n = 0; n < NACC; n++)
            wmma::store_matrix_sync(stage + (wm * 32 + m * 16) * LDS_S + wn * (TN / 2) + n * 16,
                                    acc[m][n], LDS_S, wmma::mem_row_major);
    __syncthreads();
    int r = t >> 1, ch = (t & 1) * (TN / 2);
    const float* srow = stage + r * LDS_S + ch;
    if (sg.flags & F_SCATTER) {
        int m = rb + r, b = m >> 10, mm = m & 1023;
        int s = sg.ei[(b * 2) * Mm + mm];
        float* dst = sg.agg + ((size_t)(b * Nn_ + s)) * WE_ + cb + ch;
        #pragma unroll 8
        for (int q = 0; q < TN / 2; q++) {
            float v = fmaxf(srow[q], 0.f);
            if (v != 0.f) atomicAdd(dst + q, v);
        }
    } else if (sg.flags & F_SPLIT) {
        size_t base = (size_t)(rb + r) * sg.ldc + sg.colOff + cb + ch;
        uint32_t* CH = (uint32_t*)(sg.Ch + base);
        uint32_t* CL = (uint32_t*)(sg.Cl + base);
        #pragma unroll 4
        for (int q = 0; q < TN / 4; q++) {
            float v0 = srow[2 * q], v1 = srow[2 * q + 1];
            if (sg.flags & F_RELU) { v0 = fmaxf(v0, 0.f); v1 = fmaxf(v1, 0.f); }
            bf16 h0 = __float2bfloat16(v0), h1 = __float2bfloat16(v1);
            float l0 = v0 - __bfloat162float(h0), l1 = v1 - __bfloat162float(h1);
            CH[q] = (uint32_t)__bfloat16_as_ushort(h0) | ((uint32_t)__bfloat16_as_ushort(h1) << 16);
            CL[q] = bfpack(l0, l1);
        }
    } else if (sg.flags & F_NODEADD) {
        int pair = rb + r, b = pair >> 9, p = pair & 511;
        int p0 = sg.ei[((size_t)b * Pp + p) * 2 + 0];
        int p1 = sg.ei[((size_t)b * Pp + p) * 2 + 1];
        int gc0 = cb + ch;
        const float* np0 = sg.agg + ((size_t)(b * Nn_ + p0)) * 768 + gc0;
        const float* np1 = sg.agg + ((size_t)(b * Nn_ + p1)) * 768 + gc0;
        float* crow = sg.Cf + (size_t)pair * sg.ldc + gc0;
        #pragma unroll 4
        for (int q = 0; q < TN / 8; q++) {
            float4 v = *(const float4*)(srow + q * 4);
            float4 a = *(const float4*)(np0 + q * 4);
            float4 c2 = *(const float4*)(np1 + q * 4);
            v.x = fmaxf(v.x + a.x + c2.x + sg.bias[gc0 + q * 4 + 0], 0.f);
            v.y = fmaxf(v.y + a.y + c2.y + sg.bias[gc0 + q * 4 + 1], 0.f);
            v.z = fmaxf(v.z + a.z + c2.z + sg.bias[gc0 + q * 4 + 2], 0.f);
            v.w = fmaxf(v.w + a.w + c2.w + sg.bias[gc0 + q * 4 + 3], 0.f);
            *(float4*)(crow + q * 4) = v;
        }
    } else {
        float* crow = sg.Cf + (size_t)(rb + r) * sg.ldc + cb + ch;
        #pragma unroll 4
        for (int q = 0; q < TN / 8; q++) {
            float4 v = *(const float4*)(srow + q * 4);
            if (sg.flags & F_BIAS) {
                int gc = cb + ch + q * 4;
                v.x += sg.bias[gc + 0]; v.y += sg.bias[gc + 1];
                v.z += sg.bias[gc + 2]; v.w += sg.bias[gc + 3];
            }
            if (sg.flags & F_RELU) {
                v.x = fmaxf(v.x, 0.f); v.y = fmaxf(v.y, 0.f);
                v.z = fmaxf(v.z, 0.f); v.w = fmaxf(v.w, 0.f);
            }
            *(float4*)(crow + q * 4) = v;
        }
    }
}

// ---------------- K5: pair Pm + agg*mask, 4 rows/block, float2 ----------------
__global__ void k_ci(const int* __restrict__ op, const int* __restrict__ nob) {
    int bid = blockIdx.x, t = threadIdx.x;   // 256 threads
    int sub = t >> 6, tt = (t & 63) * 2;     // 4 rows/block, 2 cols/thread
    if (bid < 2048) {                        // ---- Pm: pairs ----
        int pr = bid * 4 + sub;
        int b = pr >> 9, p = pr & 511;
        int p0 = op[((size_t)b * Pp + p) * 2 + 0];
        int p1 = op[((size_t)b * Pp + p) * 2 + 1];
        float2 x0 = *(const float2*)(d_Xp + ((size_t)b * Nn_ + p0) * WN_ + tt);
        float2 x1 = *(const float2*)(d_Xp + ((size_t)b * Nn_ + p1) * WN_ + tt);
        float v0 = fmaxf(x0.x + x1.x, 0.f);
        float v1 = fmaxf(x0.y + x1.y, 0.f);
        size_t base = (size_t)pr * 256 + tt;
        bf16 h0 = __float2bfloat16(v0), h1 = __float2bfloat16(v1);
        *(uint32_t*)(d_ciPh + base) =
            (uint32_t)__bfloat16_as_ushort(h0) | ((uint32_t)__bfloat16_as_ushort(h1) << 16);
        *(uint32_t*)(d_ciPl + base) =
            bfpack(v0 - __bfloat162float(h0), v1 - __bfloat162float(h1));
    } else {                                 // ---- nodecat agg half ----
        int row = (bid - 2048) * 4 + sub;
        int b = row >> 7, i = row & 127;
        float m = (i < nob[b]) ? 1.f : 0.f;
        float2 a = *(const float2*)(d_agg + (size_t)row * 128 + tt);
        float v0 = a.x * m, v1 = a.y * m;
        size_t base = (size_t)row * 256 + 128 + tt;
        bf16 h0 = __float2bfloat16(v0), h1 = __float2bfloat16(v1);
        *(uint32_t*)(d_ncH + base) =
            (uint32_t)__bfloat16_as_ushort(h0) | ((uint32_t)__bfloat16_as_ushort(h1) << 16);
        *(uint32_t*)(d_ncL + base) =
            bfpack(v0 - __bfloat162float(h0), v1 - __bfloat162float(h1));
    }
}

// ---------------- K7: MLP layer 2, three heads fused (one row/block) ----------
__global__ void k_head(const float* __restrict__ Wl, const float* __restrict__ bl,
                       const float* __restrict__ Wc, const float* __restrict__ bc,
                       const float* __restrict__ Wm, const float* __restrict__ bm,
                       float* __restrict__ out) {
    int r = blockIdx.x;
    int t = threadIdx.x;        // 256
    __shared__ float hs[768];
    for (int c = t; c < 768; c += 256) hs[c] = d_hid[(size_t)r * 768 + c];
    __syncthreads();
    int o = t >> 3, l = t & 7;
    const float* W; const float* bb; const float* hrow; int od, oc; float* dst;
    if (o < 9)       { W = Wl; bb = bl; hrow = hs;       od = 9;  oc = o;      dst = out +          (size_t)r * 9  + oc; }
    else if (o < 15) { W = Wc; bb = bc; hrow = hs + 256; od = 6;  oc = o - 9;  dst = out + 73728  + (size_t)r * 6  + oc; }
    else             { W = Wm; bb = bm; hrow = hs + 512; od = 17; oc = o - 15; dst = out + 122880 + (size_t)r * 17 + oc; }
    float s = 0.f;
    for (int k = l; k < 256; k += 8) s += hrow[k] * W[(size_t)k * od + oc];
    #pragma unroll
    for (int off = 4; off; off >>= 1) s += __shfl_down_sync(0xffffffffu, s, off, 8);
    if (l == 0) *dst = s + bb[oc];
}

// ---------------- launch -----------------------------------------------------
extern "C" void kernel_launch(void* const* d_in, const int* in_sizes, int n_in,
                              void* d_out, int out_size) {
    const float* nf   = (const float*)d_in[0];
    const float* ef   = (const float*)d_in[1];
    const float* adj  = (const float*)d_in[2];
    const float* ladj = (const float*)d_in[3];
    const int*   ei   = (const int*)  d_in[4];
    const int*   op   = (const int*)  d_in[5];
    const int*   nob  = (const int*)  d_in[6];
    const int*   ned  = (const int*)  d_in[7];
    const float* Wn   = (const float*)d_in[8];
    const float* We   = (const float*)d_in[9];
    const float* Wn2  = (const float*)d_in[10];
    const float* We2  = (const float*)d_in[11];
    const float* scrW1= (const float*)d_in[12];
    const float* scrb1= (const float*)d_in[13];
    const float* scrW2= (const float*)d_in[14];
    const float* scrb2= (const float*)d_in[15];
    const float* lrW1 = (const float*)d_in[16];
    const float* lrb1 = (const float*)d_in[17];
    const float* lrW2 = (const float*)d_in[18];
    const float* lrb2 = (const float*)d_in[19];
    const float* mrW1 = (const float*)d_in[20];
    const float* mrb1 = (const float*)d_in[21];
    const float* mrW2 = (const float*)d_in[22];
    const float* mrb2 = (const float*)d_in[23];
    float* out = (float*)d_out;

    bf16 *pWtH, *pWtL, *pT1h, *pT1l, *pT2h, *pT2l, *pXh, *pXl, *pEfph, *pEfpl;
    bf16 *pNcH, *pNcL, *pCiPh, *pCiPl;
    float *pXp, *pAgg, *pHid, *pB1, *pNp;
    cudaGetSymbolAddress((void**)&pWtH, d_WtH);
    cudaGetSymbolAddress((void**)&pWtL, d_WtL);
    cudaGetSymbolAddress((void**)&pT1h, d_T1h);
    cudaGetSymbolAddress((void**)&pT1l, d_T1l);
    cudaGetSymbolAddress((void**)&pT2h, d_T2h);
    cudaGetSymbolAddress((void**)&pT2l, d_T2l);
    cudaGetSymbolAddress((void**)&pXh,  d_Xh);
    cudaGetSymbolAddress((void**)&pXl,  d_Xl);
    cudaGetSymbolAddress((void**)&pEfph,d_efph);
    cudaGetSymbolAddress((void**)&pEfpl,d_efpl);
    cudaGetSymbolAddress((void**)&pNcH, d_ncH);
    cudaGetSymbolAddress((void**)&pNcL, d_ncL);
    cudaGetSymbolAddress((void**)&pCiPh,d_ciPh);
    cudaGetSymbolAddress((void**)&pCiPl,d_ciPl);
    cudaGetSymbolAddress((void**)&pXp,  d_Xp);
    cudaGetSymbolAddress((void**)&pAgg, d_agg);
    cudaGetSymbolAddress((void**)&pHid, d_hid);
    cudaGetSymbolAddress((void**)&pB1,  d_b1cat);
    cudaGetSymbolAddress((void**)&pNp,  d_nodeproj);

    const int SMEM64  = 2 * (2 * 10240 + 2 * 64 * 80);    // 61440
    const int SMEM128 = 2 * (2 * 10240 + 2 * 128 * 80);   // 81920
    cudaFuncSetAttribute(wgemm_multi<64, 3>,  cudaFuncAttributeMaxDynamicSharedMemorySize, SMEM64);
    cudaFuncSetAttribute(wgemm_multi<128, 2>, cudaFuncAttributeMaxDynamicSharedMemorySize, SMEM128);

    // d_Wt layout (elems): We[0,32768) Wn[32768,98304) Wn2[98304,163840)
    //                      We2[163840,196608) Wa[196608,393216) Wb[393216,589824)
    const int oWe = 0, oWn = 32768, oWn2 = 98304, oWe2 = 163840, oWa = 196608, oWb = 393216;
    WtTab wt;
    const float* Ws[10] = {We, Wn, Wn2, We2,
                           lrW1, lrW1 + 256 * 256,
                           scrW1, scrW1 + 256 * 256,
                           mrW1, mrW1 + 256 * 256};
    int Ks[10] = {256, 512, 512, 256, 256, 256, 256, 256, 256, 256};
    int Ns[10] = {128, 128, 128, 128, 256, 256, 256, 256, 256, 256};
    int offs[10] = {oWe, oWn, oWn2, oWe2,
                    oWa, oWb, oWa + 65536, oWb + 65536, oWa + 131072, oWb + 131072};
    int bs = 0;
    for (int i = 0; i < 10; i++) {
        wt.W[i] = Ws[i]; wt.K[i] = Ks[i]; wt.N[i] = Ns[i]; wt.off[i] = offs[i];
        wt.blkStart[i] = bs;
        bs += (Ks[i] * Ns[i]) / 256;
    }
    wt.blkStart[10] = bs;
    wt.b0 = lrb1; wt.b1 = scrb1; wt.b2 = mrb1;

    // ---- L1: weights + prep (one launch) ----
    int megaBlocks = bs + 3 + 2048 + 8192 + 1024;
    k_mega1<<<megaBlocks, 256>>>(wt, pWtH, pWtL, pB1, nf, adj, nob, ef, op);

    // ---- L2: line-graph SpMM, gathers straight from ef ----
    k_lspmm<<<dim3(Mm, Bc), 256>>>(ladj, ned, ef, ei);

    // ---- L3: wave-1 (TN=64): g(scatter) + h(->nodecat split) + Xp + Q(->ciP) -
    SegTable t4 = {};
    t4.nseg = 4;
    t4.s[0] = {pT1h, pT1l, pWtH + oWe, pWtL + oWe, nullptr, nullptr, nullptr, nullptr,
               ei, pAgg, 256, 0, 0, F_RELU | F_SCATTER, 2, 256};
    t4.s[1] = {pT2h, pT2l, pWtH + oWn, pWtL + oWn, nullptr, nullptr, pNcH, pNcL,
               nullptr, nullptr, 512, 256, 0, F_RELU | F_SPLIT, 2, 288};
    t4.s[2] = {pXh, pXl, pWtH + oWn2, pWtL + oWn2, nullptr, pXp, nullptr, nullptr,
               nullptr, nullptr, 512, 128, 0, 0, 2, 320};
    t4.s[3] = {pEfph, pEfpl, pWtH + oWe2, pWtL + oWe2, nullptr, nullptr, pCiPh, pCiPl,
               nullptr, nullptr, 256, 256, 128, F_RELU | F_SPLIT, 2, 448};
    wgemm_multi<64, 3><<<448, 256, SMEM64>>>(t4);

    // ---- L4: ciP Pm + nodecat agg-half (4 rows/block, float2) ----
    k_ci<<<2560, 256>>>(op, nob);

    // ---- L5: node GEMM: nodeproj = nodecat @ Wa  [2048 x 768 x 256] ----
    SegTable tn = {};
    tn.nseg = 1;
    tn.s[0] = {pNcH, pNcL, pWtH + oWa, pWtL + oWa, nullptr, pNp, nullptr, nullptr,
               nullptr, nullptr, 256, 768, 0, 0, 12, 192};
    wgemm_multi<64, 3><<<192, 256, SMEM64>>>(tn);

    // ---- L6: pair GEMM: hid = relu(ciP @ Wb + np[p0] + np[p1] + b) ----------
    SegTable tp = {};
    tp.nseg = 1;
    tp.s[0] = {pCiPh, pCiPl, pWtH + oWb, pWtL + oWb, pB1, pHid, nullptr, nullptr,
               op, pNp, 256, 768, 0, F_RELU | F_BIAS | F_NODEADD, 6, 384};
    wgemm_multi<128, 2><<<384, 256, SMEM128>>>(tp);

    // ---- L7: MLP layer 2 -> out (one row per block) ----
    k_head<<<Bc*Pp, 256>>>(lrW2, lrb2, scrW2, scrb2, mrW2, mrb2, out);
}